// round 11
// baseline (speedup 1.0000x reference)
#include <cuda_runtime.h>
#include <cuda_bf16.h>
#include <cstdint>

#define B_   32
#define T_   8
#define BT_  256
#define H_   14
#define W_   14
#define P_   196
#define L_   197
#define C_   768
#define CA_  384
#define M_   (BT_*P_)   // 50176

// ---- scratch (static __device__ arrays: allocation-free) ----
__device__ __nv_bfloat16 g_W1b[CA_ * C_];          // W1 bf16
__device__ __nv_bfloat16 g_W2b[C_ * CA_];          // W2 bf16
__device__ __nv_bfloat16 g_h[(size_t)M_ * CA_];    // fc1 out          (38.5 MB)
__device__ __nv_bfloat16 g_g[(size_t)M_ * CA_];    // conv out         (38.5 MB)

// ---------------- helpers ----------------
__device__ __forceinline__ uint32_t smem_u32(const void* p) {
    return (uint32_t)__cvta_generic_to_shared(p);
}

__device__ __forceinline__ void cp16(void* sdst, const void* gsrc) {
    uint32_t d = smem_u32(sdst);
    asm volatile("cp.async.cg.shared.global [%0], [%1], 16;\n" :: "r"(d), "l"(gsrc));
}

__device__ __forceinline__ void ldsm4(uint32_t& r0, uint32_t& r1, uint32_t& r2, uint32_t& r3, uint32_t addr) {
    asm volatile("ldmatrix.sync.aligned.m8n8.x4.shared.b16 {%0,%1,%2,%3}, [%4];\n"
                 : "=r"(r0), "=r"(r1), "=r"(r2), "=r"(r3) : "r"(addr));
}

__device__ __forceinline__ void mma_bf16(float (&d)[4], const uint32_t (&a)[4], const uint32_t (&b)[2]) {
    asm volatile(
        "mma.sync.aligned.m16n8k16.row.col.f32.bf16.bf16.f32 "
        "{%0,%1,%2,%3}, {%4,%5,%6,%7}, {%8,%9}, {%0,%1,%2,%3};\n"
        : "+f"(d[0]), "+f"(d[1]), "+f"(d[2]), "+f"(d[3])
        : "r"(a[0]), "r"(a[1]), "r"(a[2]), "r"(a[3]), "r"(b[0]), "r"(b[1]));
}

// ---------------- prep kernels ----------------
__global__ void prep_weights(const float* __restrict__ W1, const float* __restrict__ W2) {
    int i = blockIdx.x * 256 + threadIdx.x;
    g_W1b[i] = __float2bfloat16(W1[i]);
    g_W2b[i] = __float2bfloat16(W2[i]);
}

__global__ void cls_copy(const float4* __restrict__ x4, float4* __restrict__ o4) {
    int i = blockIdx.x * 256 + threadIdx.x;
    int bt = i / (C_ / 4);
    int j = i - bt * (C_ / 4);
    size_t off = (size_t)bt * L_ * (C_ / 4) + j;
    o4[off] = x4[off];
}

#define GBM 128
#define GBN 128
#define GBK 32
#define GSTAGES 4
#define GPITCH 40            // bf16 elems per smem row (32 + 8 pad)
#define GTILE_B (GBM * GPITCH * 2)            // 10240 per tile half
#define FC1_SMEM (2 * GTILE_B + 4 * GTILE_B)  // A ring(2) + B stages(4) = 61440
#define FC2_SMEM (GSTAGES * 2 * GTILE_B)      // 81920

// ---------------- fc1 GEMM: A = fp32 x (fused gather+convert), B = g_W1b ----------------
__global__ __launch_bounds__(256, 2)
void gemm_fc1(const float* __restrict__ x, const float* __restrict__ bias) {
    constexpr int KD = C_;
    constexpr int NK = KD / GBK;   // 24
    extern __shared__ char smem[];
    char* sAr = smem;                   // 2-stage A ring
    char* sBs = smem + 2 * GTILE_B;     // 4-stage B

    const int tid  = threadIdx.x;
    const int lane = tid & 31;
    const int warp = tid >> 5;
    const int bm = blockIdx.y * GBM;
    const int bn = blockIdx.x * GBN;
    const int wm0 = (warp >> 2) * 64;
    const int wn0 = (warp & 3) * 32;

    // B copy: thread -> rows rB0, rB0+64, chunk cB0
    const int rB0 = tid >> 2, cB0 = tid & 3;
    auto issueB = [&](int kt) {
        char* st = sBs + (size_t)(kt & 3) * GTILE_B;
        const __nv_bfloat16* gB = g_W1b + (size_t)(bn + rB0) * KD + kt * GBK + cB0 * 8;
        cp16(st + rB0 * 80 + cB0 * 16, gB);
        cp16(st + (rB0 + 64) * 80 + cB0 * 16, gB + (size_t)64 * KD);
    };

    // A loader: thread -> row ar, half ah (16 floats)
    const int ar = tid >> 1, ah = tid & 1;
    const int gr = bm + ar;
    const int srow = gr + gr / P_ + 1;
    const float* asrc = x + (size_t)srow * C_ + ah * 16;

    float a32[16];
    auto ldgA = [&](int kt) {
        const float4* p = (const float4*)(asrc + kt * GBK);
        #pragma unroll
        for (int i = 0; i < 4; ++i) {
            float4 v = __ldg(p + i);
            a32[4 * i + 0] = v.x; a32[4 * i + 1] = v.y;
            a32[4 * i + 2] = v.z; a32[4 * i + 3] = v.w;
        }
    };
    auto stsA = [&](int kt) {
        __nv_bfloat162 hb[8];
        #pragma unroll
        for (int i = 0; i < 8; ++i)
            hb[i] = __floats2bfloat162_rn(a32[2 * i], a32[2 * i + 1]);
        char* dst = sAr + (size_t)(kt & 1) * GTILE_B + ar * 80 + ah * 32;
        ((uint4*)dst)[0] = ((const uint4*)hb)[0];
        ((uint4*)dst)[1] = ((const uint4*)hb)[1];
    };

    // prologue
    #pragma unroll
    for (int s = 0; s < GSTAGES - 1; ++s) {
        issueB(s);
        asm volatile("cp.async.commit_group;\n" ::: "memory");
    }
    ldgA(0);
    stsA(0);

    float acc[4][4][4];
    #pragma unroll
    for (int mt = 0; mt < 4; ++mt)
        #pragma unroll
        for (int nt = 0; nt < 4; ++nt)
            #pragma unroll
            for (int i = 0; i < 4; ++i) acc[mt][nt][i] = 0.0f;

    const int a_row = lane & 15;
    const int a_col = (lane >> 4) << 3;
    const int b_row = lane & 7;
    const int b_sub = (lane >> 4);
    const int b_col = ((lane >> 3) & 1) << 3;

    uint32_t af[2][4][4];
    uint32_t bf[2][4][2];

    auto load_frags = [&](int kt, int ks, int buf) {
        uint32_t sA = smem_u32(sAr + (size_t)(kt & 1) * GTILE_B);
        uint32_t sB = smem_u32(sBs + (size_t)(kt & 3) * GTILE_B);
        #pragma unroll
        for (int mt = 0; mt < 4; ++mt) {
            uint32_t addr = sA + 2u * ((wm0 + mt * 16 + a_row) * GPITCH + ks * 16 + a_col);
            ldsm4(af[buf][mt][0], af[buf][mt][1], af[buf][mt][2], af[buf][mt][3], addr);
        }
        #pragma unroll
        for (int p = 0; p < 2; ++p) {
            uint32_t addr = sB + 2u * ((wn0 + (p * 2 + b_sub) * 8 + b_row) * GPITCH + ks * 16 + b_col);
            ldsm4(bf[buf][p * 2][0], bf[buf][p * 2][1], bf[buf][p * 2 + 1][0], bf[buf][p * 2 + 1][1], addr);
        }
    };

    asm volatile("cp.async.wait_group %0;\n" :: "n"(GSTAGES - 2) : "memory");
    __syncthreads();        // B(0) ready + A(0) STS visible
    load_frags(0, 0, 0);

    for (int kt = 0; kt < NK; ++kt) {
        load_frags(kt, 1, 1);
        if (kt + 1 < NK) ldgA(kt + 1);
        if (kt + GSTAGES - 1 < NK) issueB(kt + GSTAGES - 1);
        asm volatile("cp.async.commit_group;\n" ::: "memory");   // empty commit ok in tail

        #pragma unroll
        for (int mt = 0; mt < 4; ++mt)
            #pragma unroll
            for (int nt = 0; nt < 4; ++nt)
                mma_bf16(acc[mt][nt], af[0][mt], bf[0][nt]);

        asm volatile("cp.async.wait_group %0;\n" :: "n"(GSTAGES - 2) : "memory");
        __syncthreads();                 // B(kt+1) ready; A ring slot (kt+1)&1 free
        if (kt + 1 < NK) stsA(kt + 1);
        __syncthreads();                 // A(kt+1) visible
        if (kt + 1 < NK) load_frags(kt + 1, 0, 0);

        #pragma unroll
        for (int mt = 0; mt < 4; ++mt)
            #pragma unroll
            for (int nt = 0; nt < 4; ++nt)
                mma_bf16(acc[mt][nt], af[1][mt], bf[1][nt]);
    }

    // epilogue -> g_h bf16 (+bias)
    const int er = lane >> 2;
    const int ec = (lane & 3) << 1;
    #pragma unroll
    for (int mt = 0; mt < 4; ++mt) {
        #pragma unroll
        for (int nt = 0; nt < 4; ++nt) {
            const int n0 = bn + wn0 + nt * 8 + ec;
            const float bv0 = __ldg(&bias[n0]);
            const float bv1 = __ldg(&bias[n0 + 1]);
            #pragma unroll
            for (int i = 0; i < 2; ++i) {
                const int m = bm + wm0 + mt * 16 + er + i * 8;
                const float v0 = acc[mt][nt][i * 2 + 0] + bv0;
                const float v1 = acc[mt][nt][i * 2 + 1] + bv1;
                *(__nv_bfloat162*)(g_h + (size_t)m * CA_ + n0) = __floats2bfloat162_rn(v0, v1);
            }
        }
    }
}

// ---------------- fc2 GEMM (unchanged R4 pipeline): A=g_g, B=g_W2b -> out + residual ----------------
__global__ __launch_bounds__(256, 2)
void gemm_fc2(const float* __restrict__ bias,
              const float* __restrict__ xres,
              float* __restrict__ outf) {
    constexpr int KD = CA_;
    constexpr int NK = KD / GBK;
    const __nv_bfloat16* __restrict__ A  = g_g;
    const __nv_bfloat16* __restrict__ Bw = g_W2b;

    extern __shared__ char smem[];
    const int tid  = threadIdx.x;
    const int lane = tid & 31;
    const int warp = tid >> 5;
    const int bm = blockIdx.y * GBM;
    const int bn = blockIdx.x * GBN;
    const int wm0 = (warp >> 2) * 64;
    const int wn0 = (warp & 3) * 32;

    const int rA0 = tid >> 2, cA0 = tid & 3;

    auto issue = [&](int kt) {
        const int k0 = kt * GBK;
        char* st = smem + (size_t)(kt & (GSTAGES - 1)) * (2 * GTILE_B);
        const __nv_bfloat16* gA = A + (size_t)(bm + rA0) * KD + k0 + cA0 * 8;
        cp16(st + rA0 * 80 + cA0 * 16, gA);
        cp16(st + (rA0 + 64) * 80 + cA0 * 16, gA + (size_t)64 * KD);
        char* stB = st + GTILE_B;
        const __nv_bfloat16* gB = Bw + (size_t)(bn + rA0) * KD + k0 + cA0 * 8;
        cp16(stB + rA0 * 80 + cA0 * 16, gB);
        cp16(stB + (rA0 + 64) * 80 + cA0 * 16, gB + (size_t)64 * KD);
    };

    #pragma unroll
    for (int s = 0; s < GSTAGES - 1; ++s) {
        issue(s);
        asm volatile("cp.async.commit_group;\n" ::: "memory");
    }

    float acc[4][4][4];
    #pragma unroll
    for (int mt = 0; mt < 4; ++mt)
        #pragma unroll
        for (int nt = 0; nt < 4; ++nt)
            #pragma unroll
            for (int i = 0; i < 4; ++i) acc[mt][nt][i] = 0.0f;

    const int a_row = lane & 15;
    const int a_col = (lane >> 4) << 3;
    const int b_row = lane & 7;
    const int b_sub = (lane >> 4);
    const int b_col = ((lane >> 3) & 1) << 3;

    uint32_t af[2][4][4];
    uint32_t bf[2][4][2];

    auto load_frags = [&](int kt, int ks, int buf) {
        uint32_t sA = smem_u32(smem + (size_t)(kt & (GSTAGES - 1)) * (2 * GTILE_B));
        uint32_t sB = sA + GTILE_B;
        #pragma unroll
        for (int mt = 0; mt < 4; ++mt) {
            uint32_t addr = sA + 2u * ((wm0 + mt * 16 + a_row) * GPITCH + ks * 16 + a_col);
            ldsm4(af[buf][mt][0], af[buf][mt][1], af[buf][mt][2], af[buf][mt][3], addr);
        }
        #pragma unroll
        for (int p = 0; p < 2; ++p) {
            uint32_t addr = sB + 2u * ((wn0 + (p * 2 + b_sub) * 8 + b_row) * GPITCH + ks * 16 + b_col);
            ldsm4(bf[buf][p * 2][0], bf[buf][p * 2][1], bf[buf][p * 2 + 1][0], bf[buf][p * 2 + 1][1], addr);
        }
    };

    asm volatile("cp.async.wait_group %0;\n" :: "n"(GSTAGES - 2) : "memory");
    __syncthreads();
    load_frags(0, 0, 0);

    for (int kt = 0; kt < NK; ++kt) {
        load_frags(kt, 1, 1);
        if (kt + GSTAGES - 1 < NK) issue(kt + GSTAGES - 1);
        asm volatile("cp.async.commit_group;\n" ::: "memory");

        #pragma unroll
        for (int mt = 0; mt < 4; ++mt)
            #pragma unroll
            for (int nt = 0; nt < 4; ++nt)
                mma_bf16(acc[mt][nt], af[0][mt], bf[0][nt]);

        asm volatile("cp.async.wait_group %0;\n" :: "n"(GSTAGES - 2) : "memory");
        __syncthreads();
        if (kt + 1 < NK) load_frags(kt + 1, 0, 0);

        #pragma unroll
        for (int mt = 0; mt < 4; ++mt)
            #pragma unroll
            for (int nt = 0; nt < 4; ++nt)
                mma_bf16(acc[mt][nt], af[1][mt], bf[1][nt]);
    }

    const int er = lane >> 2;
    const int ec = (lane & 3) << 1;
    #pragma unroll
    for (int mt = 0; mt < 4; ++mt) {
        #pragma unroll
        for (int nt = 0; nt < 4; ++nt) {
            const int n0 = bn + wn0 + nt * 8 + ec;
            const float bv0 = __ldg(&bias[n0]);
            const float bv1 = __ldg(&bias[n0 + 1]);
            #pragma unroll
            for (int i = 0; i < 2; ++i) {
                const int m = bm + wm0 + mt * 16 + er + i * 8;
                const int bt = m / P_;
                const size_t off = (size_t)(m + bt + 1) * C_ + n0;
                float2 xr = *(const float2*)(xres + off);
                float2 o;
                o.x = xr.x + acc[mt][nt][i * 2 + 0] + bv0;
                o.y = xr.y + acc[mt][nt][i * 2 + 1] + bv1;
                *(float2*)(outf + off) = o;
            }
        }
    }
}

// ---------------- depthwise 3x3x3 conv (smem-tiled, sliding-x window) ----------------
#define CONV_THREADS 448
#define SLAB_WORDS   (P_ * 32)            // 6272 uint32 = 25088 B
#define CONV_DATA_B  (3 * SLAB_WORDS * 4) // 75264
#define CONV_W_B     (64 * 27 * 4)        // 6912
#define CONV_SMEM_B  (CONV_DATA_B + CONV_W_B + 64 * 4)

__global__ __launch_bounds__(CONV_THREADS, 1)
void conv_kernel(const float* __restrict__ cw, const float* __restrict__ cb) {
    extern __shared__ char csm[];
    uint32_t* s_data = (uint32_t*)csm;                    // [3][196][32]
    float*    s_w    = (float*)(csm + CONV_DATA_B);       // [64][27]
    float*    s_b    = (float*)(csm + CONV_DATA_B + CONV_W_B);

    const int tid = threadIdx.x;
    const int bt  = blockIdx.x;
    const int chb = blockIdx.y * 64;
    const int t   = bt & 7;
    const int y    = tid >> 5;
    const int lane = tid & 31;

    for (int i = tid; i < 64 * 27; i += CONV_THREADS)
        s_w[i] = __ldg(&cw[(chb + i / 27) * 27 + i % 27]);
    if (tid < 64) s_b[tid] = __ldg(&cb[chb + tid]);

    bool sv[3];
    #pragma unroll
    for (int d = 0; d < 3; ++d) {
        const int tt = t + d - 1;
        sv[d] = ((unsigned)tt < (unsigned)T_);
        uint32_t* slab = s_data + d * SLAB_WORDS;
        if (sv[d]) {
            const __nv_bfloat16* src = g_h + (size_t)(bt + d - 1) * P_ * CA_ + chb;
            for (int i = tid; i < SLAB_WORDS / 4; i += CONV_THREADS) {
                const int pos = i >> 3;
                const int co  = (i & 7) * 8;
                cp16(slab + i * 4, src + (size_t)pos * CA_ + co);
            }
        } else {
            uint4 z = {0u, 0u, 0u, 0u};
            for (int i = tid; i < SLAB_WORDS / 4; i += CONV_THREADS)
                ((uint4*)slab)[i] = z;
        }
    }
    asm volatile("cp.async.commit_group;\n" ::: "memory");
    asm volatile("cp.async.wait_group 0;\n" ::: "memory");
    __syncthreads();

    const int c0 = lane * 2;
    float2 wv[27];
    #pragma unroll
    for (int j = 0; j < 27; ++j) {
        wv[j].x = s_w[c0 * 27 + j];
        wv[j].y = s_w[(c0 + 1) * 27 + j];
    }
    const float bx = s_b[c0];
    const float by = s_b[c0 + 1];

    const uint32_t* lp[9];
    bool rv[9];
    #pragma unroll
    for (int d = 0; d < 3; ++d) {
        #pragma unroll
        for (int dy = -1; dy <= 1; ++dy) {
            const int j = d * 3 + (dy + 1);
            const int y2 = y + dy;
            rv[j] = sv[d] && ((unsigned)y2 < (unsigned)H_);
            lp[j] = s_data + d * SLAB_WORDS + (rv[j] ? y2 : y) * (W_ * 32) + lane;
        }
    }

    uint32_t v0[9], v1[9], v2[9];
    #pragma unroll
    for (int j = 0; j < 9; ++j) {
        v0[j] = 0u;
        v1[j] = rv[j] ? lp[j][0] : 0u;
    }

    uint32_t* gout = (uint32_t*)(g_g + (size_t)(bt * P_ + y * W_) * CA_ + chb) + lane;

    for (int x = 0; x < W_; ++x) {
        const bool in = (x + 1) < W_;
        #pragma unroll
        for (int j = 0; j < 9; ++j)
            v2[j] = (rv[j] && in) ? lp[j][(x + 1) * 32] : 0u;

        float ax = bx, ay = by;
        #pragma unroll
        for (int j = 0; j < 9; ++j) {
            const float2 f0 = __bfloat1622float2(*(const __nv_bfloat162*)&v0[j]);
            const float2 f1 = __bfloat1622float2(*(const __nv_bfloat162*)&v1[j]);
            const float2 f2 = __bfloat1622float2(*(const __nv_bfloat162*)&v2[j]);
            ax = fmaf(wv[3 * j + 0].x, f0.x, ax);
            ay = fmaf(wv[3 * j + 0].y, f0.y, ay);
            ax = fmaf(wv[3 * j + 1].x, f1.x, ax);
            ay = fmaf(wv[3 * j + 1].y, f1.y, ay);
            ax = fmaf(wv[3 * j + 2].x, f2.x, ax);
            ay = fmaf(wv[3 * j + 2].y, f2.y, ay);
        }
        const __nv_bfloat162 r = __floats2bfloat162_rn(ax, ay);
        gout[(size_t)x * (CA_ / 2)] = *(const uint32_t*)&r;

        #pragma unroll
        for (int j = 0; j < 9; ++j) { v0[j] = v1[j]; v1[j] = v2[j]; }
    }
}

// ---------------- launch ----------------
extern "C" void kernel_launch(void* const* d_in, const int* in_sizes, int n_in,
                              void* d_out, int out_size) {
    const float* x      = (const float*)d_in[0];
    const float* W1     = (const float*)d_in[1];
    const float* b1     = (const float*)d_in[2];
    const float* conv_w = (const float*)d_in[3];
    const float* conv_b = (const float*)d_in[4];
    const float* W2     = (const float*)d_in[5];
    const float* b2     = (const float*)d_in[6];
    float* out = (float*)d_out;
    (void)in_sizes; (void)n_in; (void)out_size;

    cudaFuncSetAttribute(gemm_fc1, cudaFuncAttributeMaxDynamicSharedMemorySize, FC1_SMEM);
    cudaFuncSetAttribute(gemm_fc2, cudaFuncAttributeMaxDynamicSharedMemorySize, FC2_SMEM);
    cudaFuncSetAttribute(conv_kernel, cudaFuncAttributeMaxDynamicSharedMemorySize, CONV_SMEM_B);

    prep_weights<<<(CA_ * C_) / 256, 256>>>(W1, W2);
    cls_copy<<<(BT_ * C_ / 4) / 256, 256>>>((const float4*)x, (float4*)out);

    gemm_fc1<<<dim3(CA_ / GBN, M_ / GBM), 256, FC1_SMEM>>>(x, b1);

    conv_kernel<<<dim3(BT_, CA_ / 64), CONV_THREADS, CONV_SMEM_B>>>(conv_w, conv_b);

    gemm_fc2<<<dim3(C_ / GBN, M_ / GBM), 256, FC2_SMEM>>>(b2, x, out);
}

// round 14
// speedup vs baseline: 1.5385x; 1.5385x over previous
#include <cuda_runtime.h>
#include <cuda_bf16.h>
#include <cstdint>

#define B_   32
#define T_   8
#define BT_  256
#define H_   14
#define W_   14
#define P_   196
#define L_   197
#define C_   768
#define CA_  384
#define M_   (BT_*P_)   // 50176

// ---- scratch (static __device__ arrays: allocation-free) ----
__device__ __nv_bfloat16 g_Abf[(size_t)M_ * C_];   // x tokens, bf16   (77 MB)
__device__ __nv_bfloat16 g_W1b[CA_ * C_];          // W1 bf16
__device__ __nv_bfloat16 g_W2b[C_ * CA_];          // W2 bf16
__device__ __nv_bfloat16 g_h[(size_t)M_ * CA_];    // fc1 out          (38.5 MB)
__device__ __nv_bfloat16 g_g[(size_t)M_ * CA_];    // conv out         (38.5 MB)

// ---------------- helpers ----------------
__device__ __forceinline__ uint32_t smem_u32(const void* p) {
    return (uint32_t)__cvta_generic_to_shared(p);
}

__device__ __forceinline__ void cp16(void* sdst, const void* gsrc) {
    uint32_t d = smem_u32(sdst);
    asm volatile("cp.async.cg.shared.global [%0], [%1], 16;\n" :: "r"(d), "l"(gsrc));
}

__device__ __forceinline__ void ldsm4(uint32_t& r0, uint32_t& r1, uint32_t& r2, uint32_t& r3, uint32_t addr) {
    asm volatile("ldmatrix.sync.aligned.m8n8.x4.shared.b16 {%0,%1,%2,%3}, [%4];\n"
                 : "=r"(r0), "=r"(r1), "=r"(r2), "=r"(r3) : "r"(addr));
}

__device__ __forceinline__ void mma_bf16(float (&d)[4], const uint32_t (&a)[4], const uint32_t (&b)[2]) {
    asm volatile(
        "mma.sync.aligned.m16n8k16.row.col.f32.bf16.bf16.f32 "
        "{%0,%1,%2,%3}, {%4,%5,%6,%7}, {%8,%9}, {%0,%1,%2,%3};\n"
        : "+f"(d[0]), "+f"(d[1]), "+f"(d[2]), "+f"(d[3])
        : "r"(a[0]), "r"(a[1]), "r"(a[2]), "r"(a[3]), "r"(b[0]), "r"(b[1]));
}

// ---------------- prep kernels ----------------
__global__ void prep_weights(const float* __restrict__ W1, const float* __restrict__ W2) {
    int i = blockIdx.x * 256 + threadIdx.x;
    g_W1b[i] = __float2bfloat16(W1[i]);
    g_W2b[i] = __float2bfloat16(W2[i]);
}

// gather non-CLS tokens of x -> dense bf16 A [M_, C_]
__global__ void prep_x(const float4* __restrict__ x4) {
    size_t i = (size_t)blockIdx.x * 256 + threadIdx.x;
    if (i >= (size_t)M_ * C_ / 4) return;
    size_t e = i * 4;
    int m = (int)(e / C_);
    int k = (int)(e - (size_t)m * C_);
    int bt = m / P_;
    size_t src = ((size_t)(m + bt + 1) * C_ + k) >> 2;
    float4 v = __ldg(&x4[src]);
    __nv_bfloat162* dst = (__nv_bfloat162*)(g_Abf + e);
    dst[0] = __floats2bfloat162_rn(v.x, v.y);
    dst[1] = __floats2bfloat162_rn(v.z, v.w);
}

__global__ void cls_copy(const float4* __restrict__ x4, float4* __restrict__ o4) {
    int i = blockIdx.x * 256 + threadIdx.x;
    int bt = i / (C_ / 4);
    int j = i - bt * (C_ / 4);
    size_t off = (size_t)bt * L_ * (C_ / 4) + j;
    o4[off] = x4[off];
}

// ---------------- GEMM (bf16 mma.sync, cp.async 4-stage, frag-pipelined; R6-proven) ----------------
#define GBM 128
#define GBN 128
#define GBK 32
#define GSTAGES 4
#define GPITCH 40            // bf16 elems per smem row (32 + 8 pad)
#define GSTAGE_BYTES (2 * GBM * GPITCH * 2)   // A tile + B tile = 20480

template <int MODE>
__global__ __launch_bounds__(256, 2)
void gemm_k(const float* __restrict__ bias,
            const float* __restrict__ xres,
            float* __restrict__ outf) {
    constexpr int KD = (MODE == 0) ? C_ : CA_;
    constexpr int NK = KD / GBK;
    const __nv_bfloat16* __restrict__ A  = (MODE == 0) ? g_Abf : g_g;
    const __nv_bfloat16* __restrict__ Bw = (MODE == 0) ? g_W1b : g_W2b;

    extern __shared__ char smem[];
    const int tid  = threadIdx.x;
    const int lane = tid & 31;
    const int warp = tid >> 5;
    const int bm = blockIdx.y * GBM;
    const int bn = blockIdx.x * GBN;
    const int wm0 = (warp >> 2) * 64;
    const int wn0 = (warp & 3) * 32;

    const int rA0 = tid >> 2, cA0 = tid & 3;

    auto issue = [&](int kt) {
        const int k0 = kt * GBK;
        char* st = smem + (size_t)(kt & (GSTAGES - 1)) * GSTAGE_BYTES;
        const __nv_bfloat16* gA = A + (size_t)(bm + rA0) * KD + k0 + cA0 * 8;
        cp16(st + rA0 * 80 + cA0 * 16, gA);
        cp16(st + (rA0 + 64) * 80 + cA0 * 16, gA + (size_t)64 * KD);
        char* stB = st + GBM * GPITCH * 2;
        const __nv_bfloat16* gB = Bw + (size_t)(bn + rA0) * KD + k0 + cA0 * 8;
        cp16(stB + rA0 * 80 + cA0 * 16, gB);
        cp16(stB + (rA0 + 64) * 80 + cA0 * 16, gB + (size_t)64 * KD);
    };

    #pragma unroll
    for (int s = 0; s < GSTAGES - 1; ++s) {
        issue(s);
        asm volatile("cp.async.commit_group;\n" ::: "memory");
    }

    float acc[4][4][4];
    #pragma unroll
    for (int mt = 0; mt < 4; ++mt)
        #pragma unroll
        for (int nt = 0; nt < 4; ++nt)
            #pragma unroll
            for (int i = 0; i < 4; ++i) acc[mt][nt][i] = 0.0f;

    const int a_row = lane & 15;
    const int a_col = (lane >> 4) << 3;
    const int b_row = lane & 7;
    const int b_sub = (lane >> 4);
    const int b_col = ((lane >> 3) & 1) << 3;

    uint32_t af[2][4][4];
    uint32_t bf[2][4][2];

    auto load_frags = [&](int kt, int ks, int buf) {
        uint32_t sA = smem_u32(smem + (size_t)(kt & (GSTAGES - 1)) * GSTAGE_BYTES);
        uint32_t sB = sA + GBM * GPITCH * 2;
        #pragma unroll
        for (int mt = 0; mt < 4; ++mt) {
            uint32_t addr = sA + 2u * ((wm0 + mt * 16 + a_row) * GPITCH + ks * 16 + a_col);
            ldsm4(af[buf][mt][0], af[buf][mt][1], af[buf][mt][2], af[buf][mt][3], addr);
        }
        #pragma unroll
        for (int p = 0; p < 2; ++p) {
            uint32_t addr = sB + 2u * ((wn0 + (p * 2 + b_sub) * 8 + b_row) * GPITCH + ks * 16 + b_col);
            ldsm4(bf[buf][p * 2][0], bf[buf][p * 2][1], bf[buf][p * 2 + 1][0], bf[buf][p * 2 + 1][1], addr);
        }
    };

    asm volatile("cp.async.wait_group %0;\n" :: "n"(GSTAGES - 2) : "memory");
    __syncthreads();
    load_frags(0, 0, 0);

    for (int kt = 0; kt < NK; ++kt) {
        load_frags(kt, 1, 1);
        if (kt + GSTAGES - 1 < NK) issue(kt + GSTAGES - 1);
        asm volatile("cp.async.commit_group;\n" ::: "memory");

        #pragma unroll
        for (int mt = 0; mt < 4; ++mt)
            #pragma unroll
            for (int nt = 0; nt < 4; ++nt)
                mma_bf16(acc[mt][nt], af[0][mt], bf[0][nt]);

        asm volatile("cp.async.wait_group %0;\n" :: "n"(GSTAGES - 2) : "memory");
        __syncthreads();
        if (kt + 1 < NK) load_frags(kt + 1, 0, 0);

        #pragma unroll
        for (int mt = 0; mt < 4; ++mt)
            #pragma unroll
            for (int nt = 0; nt < 4; ++nt)
                mma_bf16(acc[mt][nt], af[1][mt], bf[1][nt]);
    }

    // epilogue
    const int er = lane >> 2;
    const int ec = (lane & 3) << 1;
    #pragma unroll
    for (int mt = 0; mt < 4; ++mt) {
        #pragma unroll
        for (int nt = 0; nt < 4; ++nt) {
            const int n0 = bn + wn0 + nt * 8 + ec;
            const float bv0 = __ldg(&bias[n0]);
            const float bv1 = __ldg(&bias[n0 + 1]);
            #pragma unroll
            for (int i = 0; i < 2; ++i) {
                const int m = bm + wm0 + mt * 16 + er + i * 8;
                const float v0 = acc[mt][nt][i * 2 + 0] + bv0;
                const float v1 = acc[mt][nt][i * 2 + 1] + bv1;
                if (MODE == 0) {
                    *(__nv_bfloat162*)(g_h + (size_t)m * CA_ + n0) = __floats2bfloat162_rn(v0, v1);
                } else {
                    const int bt = m / P_;
                    const size_t off = (size_t)(m + bt + 1) * C_ + n0;
                    float2 xr = *(const float2*)(xres + off);
                    float2 o;
                    o.x = xr.x + v0;
                    o.y = xr.y + v1;
                    *(float2*)(outf + off) = o;
                }
            }
        }
    }
}

// ---------------- depthwise 3x3x3 conv: zero-padded smem halo, tap-outer, x fully unrolled ----------------
// block: 448 threads = 14 warps; warp = y row, lane = channel pair. grid (BT_, CA_/64).
// smem data: [3][16][16][32] u32 (t-slab, padded y, padded x, channel pair) = 98304 B.
#define CONV_THREADS 448
#define CPAD_WORDS   (16 * 16 * 32)        // per padded slab: 8192 words
#define CONV_DATA_B  (3 * CPAD_WORDS * 4)  // 98304
#define CONV_W_B     (64 * 27 * 4)         // 6912
#define CONV_SMEM_B  (CONV_DATA_B + CONV_W_B + 64 * 4)

__global__ __launch_bounds__(CONV_THREADS, 1)
void conv_kernel(const float* __restrict__ cw, const float* __restrict__ cb) {
    extern __shared__ char csm[];
    uint32_t* s_data = (uint32_t*)csm;                    // [3][16][16][32]
    float*    s_w    = (float*)(csm + CONV_DATA_B);       // [64][27]
    float*    s_b    = (float*)(csm + CONV_DATA_B + CONV_W_B);

    const int tid = threadIdx.x;
    const int bt  = blockIdx.x;
    const int chb = blockIdx.y * 64;
    const int t   = bt & 7;
    const int y    = tid >> 5;        // 0..13
    const int lane = tid & 31;

    // zero-fill all padded slabs (halo included)
    {
        uint4 z = {0u, 0u, 0u, 0u};
        for (int i = tid; i < 3 * CPAD_WORDS / 4; i += CONV_THREADS)
            ((uint4*)s_data)[i] = z;
    }
    // stage weights + bias
    for (int i = tid; i < 64 * 27; i += CONV_THREADS)
        s_w[i] = __ldg(&cw[(chb + i / 27) * 27 + i % 27]);
    if (tid < 64) s_b[tid] = __ldg(&cb[chb + tid]);
    __syncthreads();   // zeros visible before cp.async overwrites interior

    // cp.async interior of each valid t-slab into padded coords (y+1, x+1)
    #pragma unroll
    for (int d = 0; d < 3; ++d) {
        const int tt = t + d - 1;
        if ((unsigned)tt < (unsigned)T_) {
            const __nv_bfloat16* src = g_h + (size_t)(bt + d - 1) * P_ * CA_ + chb;
            for (int i = tid; i < P_ * 8; i += CONV_THREADS) {  // 1568 chunks of 16B
                const int pos = i >> 3;          // 0..195
                const int co  = i & 7;
                const int yy  = pos / W_;
                const int xx  = pos - yy * W_;
                uint32_t* dst = s_data + ((d * 16 + yy + 1) * 16 + xx + 1) * 32 + co * 4;
                cp16(dst, src + (size_t)pos * CA_ + co * 8);
            }
        }
    }
    asm volatile("cp.async.commit_group;\n" ::: "memory");
    asm volatile("cp.async.wait_group 0;\n" ::: "memory");
    __syncthreads();

    const int c0 = lane * 2;
    float accx[W_], accy[W_];
    {
        const float bx = s_b[c0], by = s_b[c0 + 1];
        #pragma unroll
        for (int x = 0; x < W_; ++x) { accx[x] = bx; accy[x] = by; }
    }

    // tap-outer: 9 (dt,dy) lines; per line 16 LDS with immediate offsets, then 3x14 FMAs
    #pragma unroll
    for (int j = 0; j < 9; ++j) {
        const int d  = j / 3;
        const int dy = j % 3;               // padded row = y + dy (0-based halo)
        const uint32_t* line = s_data + ((d * 16 + y + dy) * 16) * 32 + lane;

        float fx[16], fy[16];
        #pragma unroll
        for (int xx = 0; xx < 16; ++xx) {
            const uint32_t r = line[xx * 32];
            fx[xx] = __uint_as_float(r << 16);
            fy[xx] = __uint_as_float(r & 0xffff0000u);
        }
        #pragma unroll
        for (int dx = 0; dx < 3; ++dx) {
            const float wx = s_w[c0 * 27 + j * 3 + dx];
            const float wy = s_w[(c0 + 1) * 27 + j * 3 + dx];
            #pragma unroll
            for (int x = 0; x < W_; ++x) {
                accx[x] = fmaf(wx, fx[x + dx], accx[x]);
                accy[x] = fmaf(wy, fy[x + dx], accy[x]);
            }
        }
    }

    uint32_t* gout = (uint32_t*)(g_g + (size_t)(bt * P_ + y * W_) * CA_ + chb) + lane;
    #pragma unroll
    for (int x = 0; x < W_; ++x) {
        const __nv_bfloat162 r = __floats2bfloat162_rn(accx[x], accy[x]);
        gout[(size_t)x * (CA_ / 2)] = *(const uint32_t*)&r;
    }
}

// ---------------- launch ----------------
extern "C" void kernel_launch(void* const* d_in, const int* in_sizes, int n_in,
                              void* d_out, int out_size) {
    const float* x      = (const float*)d_in[0];
    const float* W1     = (const float*)d_in[1];
    const float* b1     = (const float*)d_in[2];
    const float* conv_w = (const float*)d_in[3];
    const float* conv_b = (const float*)d_in[4];
    const float* W2     = (const float*)d_in[5];
    const float* b2     = (const float*)d_in[6];
    float* out = (float*)d_out;
    (void)in_sizes; (void)n_in; (void)out_size;

    const int smem_bytes = GSTAGES * GSTAGE_BYTES;  // 81920
    cudaFuncSetAttribute(gemm_k<0>, cudaFuncAttributeMaxDynamicSharedMemorySize, smem_bytes);
    cudaFuncSetAttribute(gemm_k<1>, cudaFuncAttributeMaxDynamicSharedMemorySize, smem_bytes);
    cudaFuncSetAttribute(conv_kernel, cudaFuncAttributeMaxDynamicSharedMemorySize, CONV_SMEM_B);

    prep_weights<<<(CA_ * C_) / 256, 256>>>(W1, W2);
    prep_x<<<(int)(((size_t)M_ * C_ / 4 + 255) / 256), 256>>>((const float4*)x);
    cls_copy<<<(BT_ * C_ / 4) / 256, 256>>>((const float4*)x, (float4*)out);

    gemm_k<0><<<dim3(CA_ / GBN, M_ / GBM), 256, smem_bytes>>>(b1, nullptr, nullptr);

    conv_kernel<<<dim3(BT_, CA_ / 64), CONV_THREADS, CONV_SMEM_B>>>(conv_w, conv_b);

    gemm_k<1><<<dim3(C_ / GBN, M_ / GBM), 256, smem_bytes>>>(b2, x, out);
}

// round 15
// speedup vs baseline: 1.5453x; 1.0044x over previous
#include <cuda_runtime.h>
#include <cuda_bf16.h>
#include <cstdint>

#define B_   32
#define T_   8
#define BT_  256
#define H_   14
#define W_   14
#define P_   196
#define L_   197
#define C_   768
#define CA_  384
#define M_   (BT_*P_)   // 50176

// ---- scratch (static __device__ arrays: allocation-free) ----
__device__ __nv_bfloat16 g_Abf[(size_t)M_ * C_];   // x tokens, bf16   (77 MB)
__device__ __nv_bfloat16 g_W1b[CA_ * C_];          // W1 bf16
__device__ __nv_bfloat16 g_W2b[C_ * CA_];          // W2 bf16
__device__ __nv_bfloat16 g_h[(size_t)M_ * CA_];    // fc1 out          (38.5 MB)
__device__ __nv_bfloat16 g_g[(size_t)M_ * CA_];    // conv out         (38.5 MB)

// ---------------- helpers ----------------
__device__ __forceinline__ uint32_t smem_u32(const void* p) {
    return (uint32_t)__cvta_generic_to_shared(p);
}

__device__ __forceinline__ void cp16(void* sdst, const void* gsrc) {
    uint32_t d = smem_u32(sdst);
    asm volatile("cp.async.cg.shared.global [%0], [%1], 16;\n" :: "r"(d), "l"(gsrc));
}

__device__ __forceinline__ void ldsm4(uint32_t& r0, uint32_t& r1, uint32_t& r2, uint32_t& r3, uint32_t addr) {
    asm volatile("ldmatrix.sync.aligned.m8n8.x4.shared.b16 {%0,%1,%2,%3}, [%4];\n"
                 : "=r"(r0), "=r"(r1), "=r"(r2), "=r"(r3) : "r"(addr));
}

__device__ __forceinline__ void mma_bf16(float (&d)[4], const uint32_t (&a)[4], const uint32_t (&b)[2]) {
    asm volatile(
        "mma.sync.aligned.m16n8k16.row.col.f32.bf16.bf16.f32 "
        "{%0,%1,%2,%3}, {%4,%5,%6,%7}, {%8,%9}, {%0,%1,%2,%3};\n"
        : "+f"(d[0]), "+f"(d[1]), "+f"(d[2]), "+f"(d[3])
        : "r"(a[0]), "r"(a[1]), "r"(a[2]), "r"(a[3]), "r"(b[0]), "r"(b[1]));
}

// ---------------- prep kernels ----------------
// merged: weight conversion (i < CA_*C_) + CLS row copy (tail range)
#define WQ_ (CA_ * C_)            // 294912
#define CQ_ (BT_ * C_ / 4)        // 49152
__global__ void prep_misc(const float* __restrict__ W1, const float* __restrict__ W2,
                          const float4* __restrict__ x4, float4* __restrict__ o4) {
    int i = blockIdx.x * 256 + threadIdx.x;
    if (i < WQ_) {
        g_W1b[i] = __float2bfloat16(W1[i]);
        g_W2b[i] = __float2bfloat16(W2[i]);
    } else {
        int j = i - WQ_;
        if (j < CQ_) {
            int bt = j / (C_ / 4);
            int k = j - bt * (C_ / 4);
            size_t off = (size_t)bt * L_ * (C_ / 4) + k;
            o4[off] = x4[off];
        }
    }
}

// gather non-CLS tokens of x -> dense bf16 A [M_, C_]
__global__ void prep_x(const float4* __restrict__ x4) {
    size_t i = (size_t)blockIdx.x * 256 + threadIdx.x;
    if (i >= (size_t)M_ * C_ / 4) return;
    size_t e = i * 4;
    int m = (int)(e / C_);
    int k = (int)(e - (size_t)m * C_);
    int bt = m / P_;
    size_t src = ((size_t)(m + bt + 1) * C_ + k) >> 2;
    float4 v = __ldg(&x4[src]);
    __nv_bfloat162* dst = (__nv_bfloat162*)(g_Abf + e);
    dst[0] = __floats2bfloat162_rn(v.x, v.y);
    dst[1] = __floats2bfloat162_rn(v.z, v.w);
}

// ---------------- GEMM (bf16 mma.sync, cp.async 4-stage, frag-pipelined; R6-proven) ----------------
#define GBM 128
#define GBN 128
#define GBK 32
#define GSTAGES 4
#define GPITCH 40            // bf16 elems per smem row (32 + 8 pad)
#define GSTAGE_BYTES (2 * GBM * GPITCH * 2)   // A tile + B tile = 20480

template <int MODE>
__global__ __launch_bounds__(256, 2)
void gemm_k(const float* __restrict__ bias,
            const float* __restrict__ xres,
            float* __restrict__ outf) {
    constexpr int KD = (MODE == 0) ? C_ : CA_;
    constexpr int NK = KD / GBK;
    const __nv_bfloat16* __restrict__ A  = (MODE == 0) ? g_Abf : g_g;
    const __nv_bfloat16* __restrict__ Bw = (MODE == 0) ? g_W1b : g_W2b;

    extern __shared__ char smem[];
    const int tid  = threadIdx.x;
    const int lane = tid & 31;
    const int warp = tid >> 5;
    const int bm = blockIdx.y * GBM;
    const int bn = blockIdx.x * GBN;
    const int wm0 = (warp >> 2) * 64;
    const int wn0 = (warp & 3) * 32;

    const int rA0 = tid >> 2, cA0 = tid & 3;

    auto issue = [&](int kt) {
        const int k0 = kt * GBK;
        char* st = smem + (size_t)(kt & (GSTAGES - 1)) * GSTAGE_BYTES;
        const __nv_bfloat16* gA = A + (size_t)(bm + rA0) * KD + k0 + cA0 * 8;
        cp16(st + rA0 * 80 + cA0 * 16, gA);
        cp16(st + (rA0 + 64) * 80 + cA0 * 16, gA + (size_t)64 * KD);
        char* stB = st + GBM * GPITCH * 2;
        const __nv_bfloat16* gB = Bw + (size_t)(bn + rA0) * KD + k0 + cA0 * 8;
        cp16(stB + rA0 * 80 + cA0 * 16, gB);
        cp16(stB + (rA0 + 64) * 80 + cA0 * 16, gB + (size_t)64 * KD);
    };

    #pragma unroll
    for (int s = 0; s < GSTAGES - 1; ++s) {
        issue(s);
        asm volatile("cp.async.commit_group;\n" ::: "memory");
    }

    float acc[4][4][4];
    #pragma unroll
    for (int mt = 0; mt < 4; ++mt)
        #pragma unroll
        for (int nt = 0; nt < 4; ++nt)
            #pragma unroll
            for (int i = 0; i < 4; ++i) acc[mt][nt][i] = 0.0f;

    const int a_row = lane & 15;
    const int a_col = (lane >> 4) << 3;
    const int b_row = lane & 7;
    const int b_sub = (lane >> 4);
    const int b_col = ((lane >> 3) & 1) << 3;

    uint32_t af[2][4][4];
    uint32_t bf[2][4][2];

    auto load_frags = [&](int kt, int ks, int buf) {
        uint32_t sA = smem_u32(smem + (size_t)(kt & (GSTAGES - 1)) * GSTAGE_BYTES);
        uint32_t sB = sA + GBM * GPITCH * 2;
        #pragma unroll
        for (int mt = 0; mt < 4; ++mt) {
            uint32_t addr = sA + 2u * ((wm0 + mt * 16 + a_row) * GPITCH + ks * 16 + a_col);
            ldsm4(af[buf][mt][0], af[buf][mt][1], af[buf][mt][2], af[buf][mt][3], addr);
        }
        #pragma unroll
        for (int p = 0; p < 2; ++p) {
            uint32_t addr = sB + 2u * ((wn0 + (p * 2 + b_sub) * 8 + b_row) * GPITCH + ks * 16 + b_col);
            ldsm4(bf[buf][p * 2][0], bf[buf][p * 2][1], bf[buf][p * 2 + 1][0], bf[buf][p * 2 + 1][1], addr);
        }
    };

    asm volatile("cp.async.wait_group %0;\n" :: "n"(GSTAGES - 2) : "memory");
    __syncthreads();
    load_frags(0, 0, 0);

    for (int kt = 0; kt < NK; ++kt) {
        load_frags(kt, 1, 1);
        if (kt + GSTAGES - 1 < NK) issue(kt + GSTAGES - 1);
        asm volatile("cp.async.commit_group;\n" ::: "memory");

        #pragma unroll
        for (int mt = 0; mt < 4; ++mt)
            #pragma unroll
            for (int nt = 0; nt < 4; ++nt)
                mma_bf16(acc[mt][nt], af[0][mt], bf[0][nt]);

        asm volatile("cp.async.wait_group %0;\n" :: "n"(GSTAGES - 2) : "memory");
        __syncthreads();
        if (kt + 1 < NK) load_frags(kt + 1, 0, 0);

        #pragma unroll
        for (int mt = 0; mt < 4; ++mt)
            #pragma unroll
            for (int nt = 0; nt < 4; ++nt)
                mma_bf16(acc[mt][nt], af[1][mt], bf[1][nt]);
    }

    // ---- epilogue ----
    const int er = lane >> 2;
    const int ec = (lane & 3) << 1;
    if (MODE == 0) {
        #pragma unroll
        for (int mt = 0; mt < 4; ++mt) {
            #pragma unroll
            for (int nt = 0; nt < 4; ++nt) {
                const int n0 = bn + wn0 + nt * 8 + ec;
                const float bv0 = __ldg(&bias[n0]);
                const float bv1 = __ldg(&bias[n0 + 1]);
                #pragma unroll
                for (int i = 0; i < 2; ++i) {
                    const int m = bm + wm0 + mt * 16 + er + i * 8;
                    *(__nv_bfloat162*)(g_h + (size_t)m * CA_ + n0) =
                        __floats2bfloat162_rn(acc[mt][nt][i * 2 + 0] + bv0,
                                              acc[mt][nt][i * 2 + 1] + bv1);
                }
            }
        }
    } else {
        // hoist skewed row offsets (8 rows per thread), batch residual loads per row-pair
        size_t roff[4][2];
        #pragma unroll
        for (int mt = 0; mt < 4; ++mt)
            #pragma unroll
            for (int i = 0; i < 2; ++i) {
                const int m = bm + wm0 + mt * 16 + er + i * 8;
                roff[mt][i] = (size_t)(m + m / P_ + 1) * C_;
            }
        float bv[4][2];
        #pragma unroll
        for (int nt = 0; nt < 4; ++nt) {
            const int n0 = bn + wn0 + nt * 8 + ec;
            bv[nt][0] = __ldg(&bias[n0]);
            bv[nt][1] = __ldg(&bias[n0 + 1]);
        }
        #pragma unroll
        for (int mt = 0; mt < 4; ++mt) {
            // batch 8 residual loads (4 nt x 2 i) before FMA/store
            float2 xr[4][2];
            #pragma unroll
            for (int nt = 0; nt < 4; ++nt) {
                const int n0 = bn + wn0 + nt * 8 + ec;
                #pragma unroll
                for (int i = 0; i < 2; ++i)
                    xr[nt][i] = __ldg((const float2*)(xres + roff[mt][i] + n0));
            }
            #pragma unroll
            for (int nt = 0; nt < 4; ++nt) {
                const int n0 = bn + wn0 + nt * 8 + ec;
                #pragma unroll
                for (int i = 0; i < 2; ++i) {
                    float2 o;
                    o.x = xr[nt][i].x + acc[mt][nt][i * 2 + 0] + bv[nt][0];
                    o.y = xr[nt][i].y + acc[mt][nt][i * 2 + 1] + bv[nt][1];
                    *(float2*)(outf + roff[mt][i] + n0) = o;
                }
            }
        }
    }
}

// ---------------- depthwise 3x3x3 conv: zero-padded smem halo, tap-outer, x fully unrolled ----------------
#define CONV_THREADS 448
#define CPAD_WORDS   (16 * 16 * 32)        // per padded slab: 8192 words
#define CONV_DATA_B  (3 * CPAD_WORDS * 4)  // 98304
#define CONV_W_B     (64 * 27 * 4)         // 6912
#define CONV_SMEM_B  (CONV_DATA_B + CONV_W_B + 64 * 4)

__global__ __launch_bounds__(CONV_THREADS, 1)
void conv_kernel(const float* __restrict__ cw, const float* __restrict__ cb) {
    extern __shared__ char csm[];
    uint32_t* s_data = (uint32_t*)csm;                    // [3][16][16][32]
    float*    s_w    = (float*)(csm + CONV_DATA_B);       // [64][27]
    float*    s_b    = (float*)(csm + CONV_DATA_B + CONV_W_B);

    const int tid = threadIdx.x;
    const int bt  = blockIdx.x;
    const int chb = blockIdx.y * 64;
    const int t   = bt & 7;
    const int y    = tid >> 5;        // 0..13
    const int lane = tid & 31;

    // zero-fill: full slab only if invalid; otherwise just the halo strips
    #pragma unroll
    for (int d = 0; d < 3; ++d) {
        const int tt = t + d - 1;
        uint32_t* slab = s_data + d * CPAD_WORDS;
        if ((unsigned)tt >= (unsigned)T_) {
            uint4 z = {0u, 0u, 0u, 0u};
            for (int i = tid; i < CPAD_WORDS / 4; i += CONV_THREADS)
                ((uint4*)slab)[i] = z;
        } else {
            uint4 z = {0u, 0u, 0u, 0u};
            // rows 0 and 15 (full): 2*16*32 = 1024 words = 256 uint4
            for (int i = tid; i < 256; i += CONV_THREADS) {
                const int r = i >> 7;            // 0..1
                const int q = i & 127;
                ((uint4*)(slab + (r * 15 * 16) * 32))[q] = z;
            }
            // cols 0 and 15, rows 1..14: 14*2*32 = 896 words = 224 uint4
            for (int i = tid; i < 224; i += CONV_THREADS) {
                const int r = 1 + (i >> 4);      // rows 1..14
                const int c = ((i >> 3) & 1) * 15;
                const int q = i & 7;
                ((uint4*)(slab + (r * 16 + c) * 32))[q] = z;
            }
        }
    }
    // stage weights + bias
    for (int i = tid; i < 64 * 27; i += CONV_THREADS)
        s_w[i] = __ldg(&cw[(chb + i / 27) * 27 + i % 27]);
    if (tid < 64) s_b[tid] = __ldg(&cb[chb + tid]);
    __syncthreads();   // zeros visible before cp.async overwrites interior

    // cp.async interior of each valid t-slab into padded coords (y+1, x+1)
    #pragma unroll
    for (int d = 0; d < 3; ++d) {
        const int tt = t + d - 1;
        if ((unsigned)tt < (unsigned)T_) {
            const __nv_bfloat16* src = g_h + (size_t)(bt + d - 1) * P_ * CA_ + chb;
            for (int i = tid; i < P_ * 8; i += CONV_THREADS) {
                const int pos = i >> 3;
                const int co  = i & 7;
                const int yy  = pos / W_;
                const int xx  = pos - yy * W_;
                uint32_t* dst = s_data + ((d * 16 + yy + 1) * 16 + xx + 1) * 32 + co * 4;
                cp16(dst, src + (size_t)pos * CA_ + co * 8);
            }
        }
    }
    asm volatile("cp.async.commit_group;\n" ::: "memory");
    asm volatile("cp.async.wait_group 0;\n" ::: "memory");
    __syncthreads();

    const int c0 = lane * 2;
    float accx[W_], accy[W_];
    {
        const float bx = s_b[c0], by = s_b[c0 + 1];
        #pragma unroll
        for (int x = 0; x < W_; ++x) { accx[x] = bx; accy[x] = by; }
    }

    #pragma unroll
    for (int j = 0; j < 9; ++j) {
        const int d  = j / 3;
        const int dy = j % 3;
        const uint32_t* line = s_data + ((d * 16 + y + dy) * 16) * 32 + lane;

        float fx[16], fy[16];
        #pragma unroll
        for (int xx = 0; xx < 16; ++xx) {
            const uint32_t r = line[xx * 32];
            fx[xx] = __uint_as_float(r << 16);
            fy[xx] = __uint_as_float(r & 0xffff0000u);
        }
        #pragma unroll
        for (int dx = 0; dx < 3; ++dx) {
            const float wx = s_w[c0 * 27 + j * 3 + dx];
            const float wy = s_w[(c0 + 1) * 27 + j * 3 + dx];
            #pragma unroll
            for (int x = 0; x < W_; ++x) {
                accx[x] = fmaf(wx, fx[x + dx], accx[x]);
                accy[x] = fmaf(wy, fy[x + dx], accy[x]);
            }
        }
    }

    uint32_t* gout = (uint32_t*)(g_g + (size_t)(bt * P_ + y * W_) * CA_ + chb) + lane;
    #pragma unroll
    for (int x = 0; x < W_; ++x) {
        const __nv_bfloat162 r = __floats2bfloat162_rn(accx[x], accy[x]);
        gout[(size_t)x * (CA_ / 2)] = *(const uint32_t*)&r;
    }
}

// ---------------- launch ----------------
extern "C" void kernel_launch(void* const* d_in, const int* in_sizes, int n_in,
                              void* d_out, int out_size) {
    const float* x      = (const float*)d_in[0];
    const float* W1     = (const float*)d_in[1];
    const float* b1     = (const float*)d_in[2];
    const float* conv_w = (const float*)d_in[3];
    const float* conv_b = (const float*)d_in[4];
    const float* W2     = (const float*)d_in[5];
    const float* b2     = (const float*)d_in[6];
    float* out = (float*)d_out;
    (void)in_sizes; (void)n_in; (void)out_size;

    const int smem_bytes = GSTAGES * GSTAGE_BYTES;  // 81920
    cudaFuncSetAttribute(gemm_k<0>, cudaFuncAttributeMaxDynamicSharedMemorySize, smem_bytes);
    cudaFuncSetAttribute(gemm_k<1>, cudaFuncAttributeMaxDynamicSharedMemorySize, smem_bytes);
    cudaFuncSetAttribute(conv_kernel, cudaFuncAttributeMaxDynamicSharedMemorySize, CONV_SMEM_B);

    prep_misc<<<(WQ_ + CQ_ + 255) / 256, 256>>>(W1, W2, (const float4*)x, (float4*)out);
    prep_x<<<(int)(((size_t)M_ * C_ / 4 + 255) / 256), 256>>>((const float4*)x);

    gemm_k<0><<<dim3(CA_ / GBN, M_ / GBM), 256, smem_bytes>>>(b1, nullptr, nullptr);

    conv_kernel<<<dim3(BT_, CA_ / 64), CONV_THREADS, CONV_SMEM_B>>>(conv_w, conv_b);

    gemm_k<1><<<dim3(C_ / GBN, M_ / GBM), 256, smem_bytes>>>(b2, x, out);
}

// round 17
// speedup vs baseline: 1.5529x; 1.0049x over previous
#include <cuda_runtime.h>
#include <cuda_bf16.h>
#include <cstdint>

#define B_   32
#define T_   8
#define BT_  256
#define H_   14
#define W_   14
#define P_   196
#define L_   197
#define C_   768
#define CA_  384
#define M_   (BT_*P_)   // 50176

// ---- scratch (static __device__ arrays: allocation-free) ----
__device__ __nv_bfloat16 g_Abf[(size_t)M_ * C_];   // x tokens, bf16   (77 MB)
__device__ __nv_bfloat16 g_W1b[CA_ * C_];          // W1 bf16
__device__ __nv_bfloat16 g_W2b[C_ * CA_];          // W2 bf16
__device__ __nv_bfloat16 g_h[(size_t)M_ * CA_];    // fc1 out          (38.5 MB)
__device__ __nv_bfloat16 g_g[(size_t)M_ * CA_];    // conv out         (38.5 MB)

// ---------------- helpers ----------------
__device__ __forceinline__ uint32_t smem_u32(const void* p) {
    return (uint32_t)__cvta_generic_to_shared(p);
}

__device__ __forceinline__ void cp16(void* sdst, const void* gsrc) {
    uint32_t d = smem_u32(sdst);
    asm volatile("cp.async.cg.shared.global [%0], [%1], 16;\n" :: "r"(d), "l"(gsrc));
}

__device__ __forceinline__ void ldsm4(uint32_t& r0, uint32_t& r1, uint32_t& r2, uint32_t& r3, uint32_t addr) {
    asm volatile("ldmatrix.sync.aligned.m8n8.x4.shared.b16 {%0,%1,%2,%3}, [%4];\n"
                 : "=r"(r0), "=r"(r1), "=r"(r2), "=r"(r3) : "r"(addr));
}

__device__ __forceinline__ void mma_bf16(float (&d)[4], const uint32_t (&a)[4], const uint32_t (&b)[2]) {
    asm volatile(
        "mma.sync.aligned.m16n8k16.row.col.f32.bf16.bf16.f32 "
        "{%0,%1,%2,%3}, {%4,%5,%6,%7}, {%8,%9}, {%0,%1,%2,%3};\n"
        : "+f"(d[0]), "+f"(d[1]), "+f"(d[2]), "+f"(d[3])
        : "r"(a[0]), "r"(a[1]), "r"(a[2]), "r"(a[3]), "r"(b[0]), "r"(b[1]));
}

// packed f32x2 helpers (Blackwell base-family PTX)
__device__ __forceinline__ uint64_t packu2(uint32_t lo, uint32_t hi) {
    uint64_t r; asm("mov.b64 %0, {%1, %2};" : "=l"(r) : "r"(lo), "r"(hi)); return r;
}
__device__ __forceinline__ uint64_t packf2(float lo, float hi) {
    uint64_t r; asm("mov.b64 %0, {%1, %2};" : "=l"(r) : "f"(lo), "f"(hi)); return r;
}
__device__ __forceinline__ void unpackf2(float& lo, float& hi, uint64_t v) {
    asm("mov.b64 {%0, %1}, %2;" : "=f"(lo), "=f"(hi) : "l"(v));
}
__device__ __forceinline__ uint64_t fma2(uint64_t a, uint64_t b, uint64_t c) {
    uint64_t d; asm("fma.rn.f32x2 %0, %1, %2, %3;" : "=l"(d) : "l"(a), "l"(b), "l"(c)); return d;
}

// ---------------- prep kernels ----------------
// merged: weight conversion (i < CA_*C_) + CLS row copy (tail range)
#define WQ_ (CA_ * C_)            // 294912
#define CQ_ (BT_ * C_ / 4)        // 49152
__global__ void prep_misc(const float* __restrict__ W1, const float* __restrict__ W2,
                          const float4* __restrict__ x4, float4* __restrict__ o4) {
    int i = blockIdx.x * 256 + threadIdx.x;
    if (i < WQ_) {
        g_W1b[i] = __float2bfloat16(W1[i]);
        g_W2b[i] = __float2bfloat16(W2[i]);
    } else {
        int j = i - WQ_;
        if (j < CQ_) {
            int bt = j / (C_ / 4);
            int k = j - bt * (C_ / 4);
            size_t off = (size_t)bt * L_ * (C_ / 4) + k;
            o4[off] = x4[off];
        }
    }
}

// gather non-CLS tokens of x -> dense bf16 A [M_, C_]; 8 elems/thread, 16B store
__global__ void prep_x(const float4* __restrict__ x4) {
    size_t i = (size_t)blockIdx.x * 256 + threadIdx.x;   // exactly M_*C_/8 threads
    size_t e = i * 8;
    int m = (int)(e / C_);
    int k = (int)(e - (size_t)m * C_);
    int bt = m / P_;
    size_t src = ((size_t)(m + bt + 1) * C_ + k) >> 2;
    float4 v0 = __ldg(&x4[src]);
    float4 v1 = __ldg(&x4[src + 1]);
    __nv_bfloat162 ob[4];
    ob[0] = __floats2bfloat162_rn(v0.x, v0.y);
    ob[1] = __floats2bfloat162_rn(v0.z, v0.w);
    ob[2] = __floats2bfloat162_rn(v1.x, v1.y);
    ob[3] = __floats2bfloat162_rn(v1.z, v1.w);
    *(uint4*)(g_Abf + e) = *(const uint4*)ob;
}

// ---------------- GEMM (bf16 mma.sync, cp.async 4-stage, frag-pipelined; R6-proven) ----------------
#define GBM 128
#define GBN 128
#define GBK 32
#define GSTAGES 4
#define GPITCH 40            // bf16 elems per smem row (32 + 8 pad)
#define GSTAGE_BYTES (2 * GBM * GPITCH * 2)   // A tile + B tile = 20480

template <int MODE>
__global__ __launch_bounds__(256, 2)
void gemm_k(const float* __restrict__ bias,
            const float* __restrict__ xres,
            float* __restrict__ outf) {
    constexpr int KD = (MODE == 0) ? C_ : CA_;
    constexpr int NK = KD / GBK;
    const __nv_bfloat16* __restrict__ A  = (MODE == 0) ? g_Abf : g_g;
    const __nv_bfloat16* __restrict__ Bw = (MODE == 0) ? g_W1b : g_W2b;

    extern __shared__ char smem[];
    const int tid  = threadIdx.x;
    const int lane = tid & 31;
    const int warp = tid >> 5;
    const int bm = blockIdx.y * GBM;
    const int bn = blockIdx.x * GBN;
    const int wm0 = (warp >> 2) * 64;
    const int wn0 = (warp & 3) * 32;

    const int rA0 = tid >> 2, cA0 = tid & 3;

    auto issue = [&](int kt) {
        const int k0 = kt * GBK;
        char* st = smem + (size_t)(kt & (GSTAGES - 1)) * GSTAGE_BYTES;
        const __nv_bfloat16* gA = A + (size_t)(bm + rA0) * KD + k0 + cA0 * 8;
        cp16(st + rA0 * 80 + cA0 * 16, gA);
        cp16(st + (rA0 + 64) * 80 + cA0 * 16, gA + (size_t)64 * KD);
        char* stB = st + GBM * GPITCH * 2;
        const __nv_bfloat16* gB = Bw + (size_t)(bn + rA0) * KD + k0 + cA0 * 8;
        cp16(stB + rA0 * 80 + cA0 * 16, gB);
        cp16(stB + (rA0 + 64) * 80 + cA0 * 16, gB + (size_t)64 * KD);
    };

    #pragma unroll
    for (int s = 0; s < GSTAGES - 1; ++s) {
        issue(s);
        asm volatile("cp.async.commit_group;\n" ::: "memory");
    }

    float acc[4][4][4];
    #pragma unroll
    for (int mt = 0; mt < 4; ++mt)
        #pragma unroll
        for (int nt = 0; nt < 4; ++nt)
            #pragma unroll
            for (int i = 0; i < 4; ++i) acc[mt][nt][i] = 0.0f;

    const int a_row = lane & 15;
    const int a_col = (lane >> 4) << 3;
    const int b_row = lane & 7;
    const int b_sub = (lane >> 4);
    const int b_col = ((lane >> 3) & 1) << 3;

    uint32_t af[2][4][4];
    uint32_t bf[2][4][2];

    auto load_frags = [&](int kt, int ks, int buf) {
        uint32_t sA = smem_u32(smem + (size_t)(kt & (GSTAGES - 1)) * GSTAGE_BYTES);
        uint32_t sB = sA + GBM * GPITCH * 2;
        #pragma unroll
        for (int mt = 0; mt < 4; ++mt) {
            uint32_t addr = sA + 2u * ((wm0 + mt * 16 + a_row) * GPITCH + ks * 16 + a_col);
            ldsm4(af[buf][mt][0], af[buf][mt][1], af[buf][mt][2], af[buf][mt][3], addr);
        }
        #pragma unroll
        for (int p = 0; p < 2; ++p) {
            uint32_t addr = sB + 2u * ((wn0 + (p * 2 + b_sub) * 8 + b_row) * GPITCH + ks * 16 + b_col);
            ldsm4(bf[buf][p * 2][0], bf[buf][p * 2][1], bf[buf][p * 2 + 1][0], bf[buf][p * 2 + 1][1], addr);
        }
    };

    asm volatile("cp.async.wait_group %0;\n" :: "n"(GSTAGES - 2) : "memory");
    __syncthreads();
    load_frags(0, 0, 0);

    for (int kt = 0; kt < NK; ++kt) {
        load_frags(kt, 1, 1);
        if (kt + GSTAGES - 1 < NK) issue(kt + GSTAGES - 1);
        asm volatile("cp.async.commit_group;\n" ::: "memory");

        #pragma unroll
        for (int mt = 0; mt < 4; ++mt)
            #pragma unroll
            for (int nt = 0; nt < 4; ++nt)
                mma_bf16(acc[mt][nt], af[0][mt], bf[0][nt]);

        asm volatile("cp.async.wait_group %0;\n" :: "n"(GSTAGES - 2) : "memory");
        __syncthreads();
        if (kt + 1 < NK) load_frags(kt + 1, 0, 0);

        #pragma unroll
        for (int mt = 0; mt < 4; ++mt)
            #pragma unroll
            for (int nt = 0; nt < 4; ++nt)
                mma_bf16(acc[mt][nt], af[1][mt], bf[1][nt]);
    }

    // ---- epilogue ----
    const int er = lane >> 2;
    const int ec = (lane & 3) << 1;
    if (MODE == 0) {
        #pragma unroll
        for (int mt = 0; mt < 4; ++mt) {
            #pragma unroll
            for (int nt = 0; nt < 4; ++nt) {
                const int n0 = bn + wn0 + nt * 8 + ec;
                const float bv0 = __ldg(&bias[n0]);
                const float bv1 = __ldg(&bias[n0 + 1]);
                #pragma unroll
                for (int i = 0; i < 2; ++i) {
                    const int m = bm + wm0 + mt * 16 + er + i * 8;
                    *(__nv_bfloat162*)(g_h + (size_t)m * CA_ + n0) =
                        __floats2bfloat162_rn(acc[mt][nt][i * 2 + 0] + bv0,
                                              acc[mt][nt][i * 2 + 1] + bv1);
                }
            }
        }
    } else {
        size_t roff[4][2];
        #pragma unroll
        for (int mt = 0; mt < 4; ++mt)
            #pragma unroll
            for (int i = 0; i < 2; ++i) {
                const int m = bm + wm0 + mt * 16 + er + i * 8;
                roff[mt][i] = (size_t)(m + m / P_ + 1) * C_;
            }
        float bv[4][2];
        #pragma unroll
        for (int nt = 0; nt < 4; ++nt) {
            const int n0 = bn + wn0 + nt * 8 + ec;
            bv[nt][0] = __ldg(&bias[n0]);
            bv[nt][1] = __ldg(&bias[n0 + 1]);
        }
        #pragma unroll
        for (int mt = 0; mt < 4; ++mt) {
            float2 xr[4][2];
            #pragma unroll
            for (int nt = 0; nt < 4; ++nt) {
                const int n0 = bn + wn0 + nt * 8 + ec;
                #pragma unroll
                for (int i = 0; i < 2; ++i)
                    xr[nt][i] = __ldg((const float2*)(xres + roff[mt][i] + n0));
            }
            #pragma unroll
            for (int nt = 0; nt < 4; ++nt) {
                const int n0 = bn + wn0 + nt * 8 + ec;
                #pragma unroll
                for (int i = 0; i < 2; ++i) {
                    float2 o;
                    o.x = xr[nt][i].x + acc[mt][nt][i * 2 + 0] + bv[nt][0];
                    o.y = xr[nt][i].y + acc[mt][nt][i * 2 + 1] + bv[nt][1];
                    *(float2*)(outf + roff[mt][i] + n0) = o;
                }
            }
        }
    }
}

// ---------------- depthwise 3x3x3 conv: padded halo smem + packed f32x2 math ----------------
#define CONV_THREADS 448
#define CPAD_WORDS   (16 * 16 * 32)        // per padded slab: 8192 words
#define CONV_DATA_B  (3 * CPAD_WORDS * 4)  // 98304
#define CONV_W_B     (64 * 27 * 4)         // 6912
#define CONV_SMEM_B  (CONV_DATA_B + CONV_W_B + 64 * 4)

__global__ __launch_bounds__(CONV_THREADS, 2)
void conv_kernel(const float* __restrict__ cw, const float* __restrict__ cb) {
    extern __shared__ char csm[];
    uint32_t* s_data = (uint32_t*)csm;                    // [3][16][16][32]
    float*    s_w    = (float*)(csm + CONV_DATA_B);       // [64][27]
    float*    s_b    = (float*)(csm + CONV_DATA_B + CONV_W_B);

    const int tid = threadIdx.x;
    const int bt  = blockIdx.x;
    const int chb = blockIdx.y * 64;
    const int t   = bt & 7;
    const int y    = tid >> 5;        // 0..13
    const int lane = tid & 31;

    // zero-fill: full slab only if invalid; otherwise just the halo strips
    #pragma unroll
    for (int d = 0; d < 3; ++d) {
        const int tt = t + d - 1;
        uint32_t* slab = s_data + d * CPAD_WORDS;
        if ((unsigned)tt >= (unsigned)T_) {
            uint4 z = {0u, 0u, 0u, 0u};
            for (int i = tid; i < CPAD_WORDS / 4; i += CONV_THREADS)
                ((uint4*)slab)[i] = z;
        } else {
            uint4 z = {0u, 0u, 0u, 0u};
            for (int i = tid; i < 256; i += CONV_THREADS) {
                const int r = i >> 7;
                const int q = i & 127;
                ((uint4*)(slab + (r * 15 * 16) * 32))[q] = z;
            }
            for (int i = tid; i < 224; i += CONV_THREADS) {
                const int r = 1 + (i >> 4);
                const int c = ((i >> 3) & 1) * 15;
                const int q = i & 7;
                ((uint4*)(slab + (r * 16 + c) * 32))[q] = z;
            }
        }
    }
    for (int i = tid; i < 64 * 27; i += CONV_THREADS)
        s_w[i] = __ldg(&cw[(chb + i / 27) * 27 + i % 27]);
    if (tid < 64) s_b[tid] = __ldg(&cb[chb + tid]);
    __syncthreads();

    #pragma unroll
    for (int d = 0; d < 3; ++d) {
        const int tt = t + d - 1;
        if ((unsigned)tt < (unsigned)T_) {
            const __nv_bfloat16* src = g_h + (size_t)(bt + d - 1) * P_ * CA_ + chb;
            for (int i = tid; i < P_ * 8; i += CONV_THREADS) {
                const int pos = i >> 3;
                const int co  = i & 7;
                const int yy  = pos / W_;
                const int xx  = pos - yy * W_;
                uint32_t* dst = s_data + ((d * 16 + yy + 1) * 16 + xx + 1) * 32 + co * 4;
                cp16(dst, src + (size_t)pos * CA_ + co * 8);
            }
        }
    }
    asm volatile("cp.async.commit_group;\n" ::: "memory");
    asm volatile("cp.async.wait_group 0;\n" ::: "memory");
    __syncthreads();

    const int c0 = lane * 2;
    uint64_t accp[W_];
    {
        const uint64_t b2 = packf2(s_b[c0], s_b[c0 + 1]);
        #pragma unroll
        for (int x = 0; x < W_; ++x) accp[x] = b2;
    }

    // tap-outer: per (dt,dy) line, 16 LDS + pack; 3x14 packed FMAs
    #pragma unroll
    for (int j = 0; j < 9; ++j) {
        const int d  = j / 3;
        const int dy = j % 3;
        const uint32_t* line = s_data + ((d * 16 + y + dy) * 16) * 32 + lane;

        uint64_t f[16];
        #pragma unroll
        for (int xx = 0; xx < 16; ++xx) {
            const uint32_t r = line[xx * 32];
            f[xx] = packu2(r << 16, r & 0xffff0000u);
        }
        #pragma unroll
        for (int dx = 0; dx < 3; ++dx) {
            const uint64_t w2 = packf2(s_w[c0 * 27 + j * 3 + dx],
                                       s_w[(c0 + 1) * 27 + j * 3 + dx]);
            #pragma unroll
            for (int x = 0; x < W_; ++x)
                accp[x] = fma2(w2, f[x + dx], accp[x]);
        }
    }

    uint32_t* gout = (uint32_t*)(g_g + (size_t)(bt * P_ + y * W_) * CA_ + chb) + lane;
    #pragma unroll
    for (int x = 0; x < W_; ++x) {
        float ax, ay;
        unpackf2(ax, ay, accp[x]);
        const __nv_bfloat162 r = __floats2bfloat162_rn(ax, ay);
        gout[(size_t)x * (CA_ / 2)] = *(const uint32_t*)&r;
    }
}

// ---------------- launch ----------------
extern "C" void kernel_launch(void* const* d_in, const int* in_sizes, int n_in,
                              void* d_out, int out_size) {
    const float* x      = (const float*)d_in[0];
    const float* W1     = (const float*)d_in[1];
    const float* b1     = (const float*)d_in[2];
    const float* conv_w = (const float*)d_in[3];
    const float* conv_b = (const float*)d_in[4];
    const float* W2     = (const float*)d_in[5];
    const float* b2     = (const float*)d_in[6];
    float* out = (float*)d_out;
    (void)in_sizes; (void)n_in; (void)out_size;

    const int smem_bytes = GSTAGES * GSTAGE_BYTES;  // 81920
    cudaFuncSetAttribute(gemm_k<0>, cudaFuncAttributeMaxDynamicSharedMemorySize, smem_bytes);
    cudaFuncSetAttribute(gemm_k<1>, cudaFuncAttributeMaxDynamicSharedMemorySize, smem_bytes);
    cudaFuncSetAttribute(conv_kernel, cudaFuncAttributeMaxDynamicSharedMemorySize, CONV_SMEM_B);

    prep_misc<<<(WQ_ + CQ_ + 255) / 256, 256>>>(W1, W2, (const float4*)x, (float4*)out);
    prep_x<<<(int)((size_t)M_ * C_ / 8 / 256), 256>>>((const float4*)x);

    gemm_k<0><<<dim3(CA_ / GBN, M_ / GBM), 256, smem_bytes>>>(b1, nullptr, nullptr);

    conv_kernel<<<dim3(BT_, CA_ / 64), CONV_THREADS, CONV_SMEM_B>>>(conv_w, conv_b);

    gemm_k<1><<<dim3(C_ / GBN, M_ / GBM), 256, smem_bytes>>>(b2, x, out);
}